// round 1
// baseline (speedup 1.0000x reference)
#include <cuda_runtime.h>

// Problem constants
#define B_  2
#define T_  4096
#define D_  768
#define H_  12
#define DK_ 64
#define M_  (B_*T_)   // 8192 rows

// Scratch (allocation-free: __device__ globals)
__device__ float g_Q[B_*H_*T_*DK_];   // [B,H,T,DK]
__device__ float g_K[B_*H_*T_*DK_];
__device__ float g_V[B_*H_*T_*DK_];
__device__ float g_O[M_*D_];          // [B*T, D] attention output

// ---------------------------------------------------------------------------
// SGEMM: C[M,N] = A[M,768] @ W[768,N=768], tiles 128x64x16, 128 thr, 8x8 micro
// mode 0/1/2: write g_Q/g_K/g_V in [B,H,T,DK] layout. mode 3: plain row-major C.
// A==nullptr -> read from g_O.
// ---------------------------------------------------------------------------
#define GM 128
#define GN 64
#define GK 16

__global__ __launch_bounds__(128) void gemm_kernel(const float* __restrict__ A,
                                                   const float* __restrict__ W,
                                                   float* __restrict__ C,
                                                   int mode) {
    __shared__ float As[GK][GM + 4];   // transposed A tile, padded
    __shared__ float Bs[GK][GN];
    const float* Ar = A ? A : g_O;

    const int tid = threadIdx.x;
    const int tx = tid & 7;            // 0..7  -> 8 cols of 8
    const int ty = tid >> 3;           // 0..15 -> 16 rows of 8
    const int m0 = blockIdx.y * GM;
    const int n0 = blockIdx.x * GN;

    float acc[8][8] = {};

    for (int k0 = 0; k0 < D_; k0 += GK) {
        // A tile: 128x16 floats = 512 float4, 4 per thread
        #pragma unroll
        for (int it = 0; it < 4; it++) {
            int idx = it * 128 + tid;          // 0..511
            int m   = idx >> 2;
            int k4  = (idx & 3) * 4;
            float4 v = *(const float4*)(Ar + (size_t)(m0 + m) * D_ + k0 + k4);
            As[k4+0][m] = v.x; As[k4+1][m] = v.y;
            As[k4+2][m] = v.z; As[k4+3][m] = v.w;
        }
        // B tile: 16x64 floats = 256 float4, 2 per thread
        #pragma unroll
        for (int it = 0; it < 2; it++) {
            int idx = it * 128 + tid;          // 0..255
            int kk  = idx >> 4;
            int c4  = (idx & 15) * 4;
            *(float4*)&Bs[kk][c4] =
                *(const float4*)(W + (size_t)(k0 + kk) * D_ + n0 + c4);
        }
        __syncthreads();

        #pragma unroll
        for (int kk = 0; kk < GK; kk++) {
            float a[8], bb[8];
            *(float4*)(a)    = *(const float4*)&As[kk][ty*8];
            *(float4*)(a+4)  = *(const float4*)&As[kk][ty*8+4];
            *(float4*)(bb)   = *(const float4*)&Bs[kk][tx*8];
            *(float4*)(bb+4) = *(const float4*)&Bs[kk][tx*8+4];
            #pragma unroll
            for (int i = 0; i < 8; i++)
                #pragma unroll
                for (int j = 0; j < 8; j++)
                    acc[i][j] = fmaf(a[i], bb[j], acc[i][j]);
        }
        __syncthreads();
    }

    if (mode == 3) {
        #pragma unroll
        for (int i = 0; i < 8; i++) {
            int m = m0 + ty*8 + i;
            float* dst = C + (size_t)m * D_ + n0 + tx*8;
            *(float4*)(dst)     = make_float4(acc[i][0], acc[i][1], acc[i][2], acc[i][3]);
            *(float4*)(dst + 4) = make_float4(acc[i][4], acc[i][5], acc[i][6], acc[i][7]);
        }
    } else {
        float* out = (mode == 0) ? g_Q : (mode == 1) ? g_K : g_V;
        // n = h*64 + dk; tile cols are 64-aligned so h is constant per block col
        int n = n0 + tx*8;
        int h  = n >> 6;
        int dk = n & 63;
        #pragma unroll
        for (int i = 0; i < 8; i++) {
            int m = m0 + ty*8 + i;            // = b*T + t
            int b = m >> 12;                  // /4096
            int t = m & 4095;
            float* dst = out + ((size_t)((b*H_ + h)*T_ + t)) * DK_ + dk;
            *(float4*)(dst)     = make_float4(acc[i][0], acc[i][1], acc[i][2], acc[i][3]);
            *(float4*)(dst + 4) = make_float4(acc[i][4], acc[i][5], acc[i][6], acc[i][7]);
        }
    }
}

// ---------------------------------------------------------------------------
// Flash attention: per block one (b, h, 128-row Q tile). Bc = 64 KV rows/step.
// 128 threads: 16(ty) x 8(tx), each owns 8x8 of S/P and 8x8 of O (DK=64).
// ---------------------------------------------------------------------------
#define BR 128
#define BC 64
#define LDQ 65
#define LDK 65
#define LDV 64
#define LDP 64

#define ATTN_SMEM_FLOATS (BR*LDQ + BC*LDK + BC*LDV + BR*LDP)
#define ATTN_SMEM_BYTES  (ATTN_SMEM_FLOATS * 4)

__global__ __launch_bounds__(128) void attn_kernel() {
    extern __shared__ float sm[];
    float* Qs = sm;                       // [128][65], pre-scaled by 1/8
    float* Ks = Qs + BR*LDQ;              // [64][65]
    float* Vs = Ks + BC*LDK;              // [64][64]
    float* Ps = Vs + BC*LDV;              // [128][64]

    const int qtile = blockIdx.x;
    const int h     = blockIdx.y;
    const int b     = blockIdx.z;
    const int tid = threadIdx.x;
    const int tx = tid & 7;
    const int ty = tid >> 3;

    const float* Qg = g_Q + ((size_t)(b*H_ + h)*T_ + (size_t)qtile*BR) * DK_;
    const float* Kg = g_K + ((size_t)(b*H_ + h)*T_) * DK_;
    const float* Vg = g_V + ((size_t)(b*H_ + h)*T_) * DK_;

    // Load Q tile (8192 floats), fold in softmax scale 1/sqrt(64)=0.125
    #pragma unroll 4
    for (int it = 0; it < 64; it++) {
        int idx = it * 128 + tid;
        int r = idx >> 6, c = idx & 63;
        Qs[r*LDQ + c] = Qg[idx] * 0.125f;
    }

    float m_i[8], l_i[8], o[8][8];
    #pragma unroll
    for (int i = 0; i < 8; i++) {
        m_i[i] = -1e30f; l_i[i] = 0.f;
        #pragma unroll
        for (int j = 0; j < 8; j++) o[i][j] = 0.f;
    }

    for (int kv0 = 0; kv0 < T_; kv0 += BC) {
        __syncthreads();   // prior PV phase done reading Ks/Vs
        #pragma unroll 4
        for (int it = 0; it < 32; it++) {
            int idx = it * 128 + tid;       // 0..4095
            int r = idx >> 6, c = idx & 63;
            Ks[r*LDK + c] = Kg[(size_t)kv0*DK_ + idx];
            Vs[r*LDV + c] = Vg[(size_t)kv0*DK_ + idx];
        }
        __syncthreads();

        // S = (Q*scale) @ K^T   (8x8 per thread)
        float s[8][8] = {};
        #pragma unroll 8
        for (int d = 0; d < DK_; d++) {
            float a[8], kb[8];
            #pragma unroll
            for (int i = 0; i < 8; i++) a[i]  = Qs[(ty*8 + i)*LDQ + d];
            #pragma unroll
            for (int j = 0; j < 8; j++) kb[j] = Ks[(tx*8 + j)*LDK + d];
            #pragma unroll
            for (int i = 0; i < 8; i++)
                #pragma unroll
                for (int j = 0; j < 8; j++)
                    s[i][j] = fmaf(a[i], kb[j], s[i][j]);
        }

        // Online softmax per row (row shared by the 8 tx lanes; shfl width 8)
        #pragma unroll
        for (int i = 0; i < 8; i++) {
            float mx = s[i][0];
            #pragma unroll
            for (int j = 1; j < 8; j++) mx = fmaxf(mx, s[i][j]);
            mx = fmaxf(mx, __shfl_xor_sync(0xffffffffu, mx, 1, 8));
            mx = fmaxf(mx, __shfl_xor_sync(0xffffffffu, mx, 2, 8));
            mx = fmaxf(mx, __shfl_xor_sync(0xffffffffu, mx, 4, 8));
            float mnew  = fmaxf(m_i[i], mx);
            float alpha = __expf(m_i[i] - mnew);
            float rs = 0.f;
            #pragma unroll
            for (int j = 0; j < 8; j++) {
                float p = __expf(s[i][j] - mnew);
                s[i][j] = p;
                rs += p;
            }
            rs += __shfl_xor_sync(0xffffffffu, rs, 1, 8);
            rs += __shfl_xor_sync(0xffffffffu, rs, 2, 8);
            rs += __shfl_xor_sync(0xffffffffu, rs, 4, 8);
            l_i[i] = l_i[i] * alpha + rs;
            m_i[i] = mnew;
            #pragma unroll
            for (int j = 0; j < 8; j++) o[i][j] *= alpha;
            // stash P row segment (contiguous float4 stores)
            float* prow = Ps + (ty*8 + i)*LDP + tx*8;
            *(float4*)(prow)     = make_float4(s[i][0], s[i][1], s[i][2], s[i][3]);
            *(float4*)(prow + 4) = make_float4(s[i][4], s[i][5], s[i][6], s[i][7]);
        }
        __syncthreads();

        // O += P @ V
        #pragma unroll 8
        for (int k = 0; k < BC; k++) {
            float pv[8], vv[8];
            #pragma unroll
            for (int i = 0; i < 8; i++) pv[i] = Ps[(ty*8 + i)*LDP + k];
            #pragma unroll
            for (int j = 0; j < 8; j++) vv[j] = Vs[k*LDV + tx*8 + j];
            #pragma unroll
            for (int i = 0; i < 8; i++)
                #pragma unroll
                for (int j = 0; j < 8; j++)
                    o[i][j] = fmaf(pv[i], vv[j], o[i][j]);
        }
    }

    // Final normalize, write O in [B,T,D] row-major (t = qtile*128 + row)
    #pragma unroll
    for (int i = 0; i < 8; i++) {
        float inv = 1.f / l_i[i];
        int t = qtile*BR + ty*8 + i;
        float* dst = g_O + ((size_t)b*T_ + t)*D_ + h*DK_ + tx*8;
        *(float4*)(dst)     = make_float4(o[i][0]*inv, o[i][1]*inv, o[i][2]*inv, o[i][3]*inv);
        *(float4*)(dst + 4) = make_float4(o[i][4]*inv, o[i][5]*inv, o[i][6]*inv, o[i][7]*inv);
    }
}

// ---------------------------------------------------------------------------
extern "C" void kernel_launch(void* const* d_in, const int* in_sizes, int n_in,
                              void* d_out, int out_size) {
    const float* x  = (const float*)d_in[0];
    const float* WQ = (const float*)d_in[1];
    const float* WK = (const float*)d_in[2];
    const float* WV = (const float*)d_in[3];
    const float* Wp = (const float*)d_in[4];
    float* out = (float*)d_out;

    cudaFuncSetAttribute(attn_kernel,
                         cudaFuncAttributeMaxDynamicSharedMemorySize,
                         ATTN_SMEM_BYTES);

    dim3 gg(D_ / GN, M_ / GM);            // (12, 64)
    gemm_kernel<<<gg, 128>>>(x, WQ, nullptr, 0);   // Q
    gemm_kernel<<<gg, 128>>>(x, WK, nullptr, 1);   // K
    gemm_kernel<<<gg, 128>>>(x, WV, nullptr, 2);   // V

    dim3 ga(T_ / BR, H_, B_);             // (32, 12, 2)
    attn_kernel<<<ga, 128, ATTN_SMEM_BYTES>>>();

    gemm_kernel<<<gg, 128>>>(nullptr, Wp, out, 3); // projection
}

// round 4
// speedup vs baseline: 3.0547x; 3.0547x over previous
#include <cuda_runtime.h>
#include <cstdint>

#define B_  2
#define T_  4096
#define D_  768
#define H_  12
#define DK_ 64
#define M_  (B_*T_)   // 8192

// Scratch (allocation-free)
__device__ float g_Q[B_*H_*T_*DK_];
__device__ float g_K[B_*H_*T_*DK_];
__device__ float g_V[B_*H_*T_*DK_];
__device__ float g_O[M_*D_];

__device__ __forceinline__ uint32_t f2tf(float f) {
    uint32_t r; asm("cvt.rna.tf32.f32 %0, %1;" : "=r"(r) : "f"(f)); return r;
}
__device__ __forceinline__ void mma8(float* c, const uint32_t* a, const uint32_t* b) {
    asm volatile("mma.sync.aligned.m16n8k8.row.col.f32.tf32.tf32.f32 "
        "{%0,%1,%2,%3}, {%4,%5,%6,%7}, {%8,%9}, {%0,%1,%2,%3};"
        : "+f"(c[0]), "+f"(c[1]), "+f"(c[2]), "+f"(c[3])
        : "r"(a[0]), "r"(a[1]), "r"(a[2]), "r"(a[3]), "r"(b[0]), "r"(b[1]));
}

// ---------------------------------------------------------------------------
// tf32 GEMM: C[8192,768] = A @ W[768,768]. Block tile 128x64, 4 warps,
// warp tile 32x64, k-tile 32. mode 0/1/2 -> g_Q/g_K/g_V ([B,H,T,DK] split,
// h == blockIdx.x since GN==DK==64); mode 3 -> row-major C.
// ---------------------------------------------------------------------------
#define LDA 36
#define LDW 68

__global__ __launch_bounds__(128) void gemm_mma(const float* __restrict__ A,
                                                const float* __restrict__ W,
                                                float* __restrict__ C, int mode) {
    __shared__ uint32_t As[128*LDA];
    __shared__ uint32_t Ws[32*LDW];
    const float* Ar = A ? A : g_O;

    const int tid = threadIdx.x;
    const int w = tid >> 5, l = tid & 31, g = l >> 2, t = l & 3;
    const int m0b = blockIdx.y * 128, n0 = blockIdx.x * 64;
    const int mw = w * 32;

    float acc[2][8][4] = {};

    for (int k0 = 0; k0 < D_; k0 += 32) {
        __syncthreads();
        #pragma unroll
        for (int it = 0; it < 8; it++) {            // A tile 128x32
            int idx = it*512 + tid*4;
            int r = idx >> 5, c = idx & 31;
            float4 v = *(const float4*)(Ar + (size_t)(m0b + r)*D_ + k0 + c);
            uint4 u = { f2tf(v.x), f2tf(v.y), f2tf(v.z), f2tf(v.w) };
            *(uint4*)&As[r*LDA + c] = u;
        }
        #pragma unroll
        for (int it = 0; it < 4; it++) {            // W tile 32x64
            int idx = it*512 + tid*4;
            int r = idx >> 6, c = idx & 63;
            float4 v = *(const float4*)(W + (size_t)(k0 + r)*D_ + n0 + c);
            uint4 u = { f2tf(v.x), f2tf(v.y), f2tf(v.z), f2tf(v.w) };
            *(uint4*)&Ws[r*LDW + c] = u;
        }
        __syncthreads();

        #pragma unroll
        for (int kt = 0; kt < 4; kt++) {
            uint32_t bf[8][2];
            #pragma unroll
            for (int nt = 0; nt < 8; nt++) {
                bf[nt][0] = Ws[(kt*8 + t    )*LDW + nt*8 + g];
                bf[nt][1] = Ws[(kt*8 + t + 4)*LDW + nt*8 + g];
            }
            #pragma unroll
            for (int mt = 0; mt < 2; mt++) {
                uint32_t af[4];
                int r = mw + mt*16 + g;
                af[0] = As[ r     *LDA + kt*8 + t    ];
                af[1] = As[(r + 8)*LDA + kt*8 + t    ];
                af[2] = As[ r     *LDA + kt*8 + t + 4];
                af[3] = As[(r + 8)*LDA + kt*8 + t + 4];
                #pragma unroll
                for (int nt = 0; nt < 8; nt++) mma8(acc[mt][nt], af, bf[nt]);
            }
        }
    }

    #pragma unroll
    for (int mt = 0; mt < 2; mt++)
    #pragma unroll
    for (int hh = 0; hh < 2; hh++) {
        int m = m0b + mw + mt*16 + hh*8 + g;
        #pragma unroll
        for (int nt = 0; nt < 8; nt++) {
            float2 v = make_float2(acc[mt][nt][hh*2], acc[mt][nt][hh*2 + 1]);
            if (mode == 3) {
                *(float2*)(C + (size_t)m*D_ + n0 + nt*8 + 2*t) = v;
            } else {
                float* out = (mode == 0) ? g_Q : (mode == 1) ? g_K : g_V;
                int b = m >> 12, tt = m & 4095;
                *(float2*)(out + ((size_t)(b*H_ + blockIdx.x)*T_ + tt)*DK_ + nt*8 + 2*t) = v;
            }
        }
    }
}

// ---------------------------------------------------------------------------
// Flash attention, tf32 mma. Block = (b, h, 128 Q rows), 4 warps, warp = 32
// rows. Bc = 64. All smem rows padded to 68 words -> fragment gathers are
// bank-conflict-free (addr mod 32 = 4g+t or 4t+g, all distinct).
// ---------------------------------------------------------------------------
#define LQ 68
#define ATTN_SMEM_BYTES ((128*LQ + 64*LQ + 64*LQ + 128*LQ) * 4)  // 104448

__global__ __launch_bounds__(128) void attn_mma() {
    extern __shared__ uint32_t sm[];
    uint32_t* Qs = sm;                 // [128][68] tf32(Q * 0.125)
    uint32_t* Ks = Qs + 128*LQ;        // [64][68]
    uint32_t* Vs = Ks + 64*LQ;         // [64][68]
    uint32_t* Ps = Vs + 64*LQ;         // [128][68]

    const int qtile = blockIdx.x, h = blockIdx.y, b = blockIdx.z;
    const int tid = threadIdx.x;
    const int w = tid >> 5, l = tid & 31, g = l >> 2, t = l & 3;
    const int mw = w * 32;

    const float* Qg = g_Q + ((size_t)(b*H_ + h)*T_ + (size_t)qtile*128) * DK_;
    const float* Kg = g_K + (size_t)(b*H_ + h)*T_ * DK_;
    const float* Vg = g_V + (size_t)(b*H_ + h)*T_ * DK_;

    #pragma unroll
    for (int it = 0; it < 16; it++) {              // Q tile 128x64
        int idx = it*512 + tid*4;
        int r = idx >> 6, c = idx & 63;
        float4 v = *(const float4*)(Qg + idx);
        uint4 u = { f2tf(v.x*0.125f), f2tf(v.y*0.125f),
                    f2tf(v.z*0.125f), f2tf(v.w*0.125f) };
        *(uint4*)&Qs[r*LQ + c] = u;
    }

    float o[2][8][4] = {};
    float mi[2][2] = {{-1e30f,-1e30f},{-1e30f,-1e30f}};
    float li[2][2] = {};

    for (int kv0 = 0; kv0 < T_; kv0 += 64) {
        __syncthreads();                           // prev PV done with Ks/Vs
        #pragma unroll
        for (int it = 0; it < 8; it++) {           // K,V tiles 64x64
            int idx = it*512 + tid*4;
            int r = idx >> 6, c = idx & 63;
            float4 kv = *(const float4*)(Kg + (size_t)kv0*DK_ + idx);
            uint4 uk = { f2tf(kv.x), f2tf(kv.y), f2tf(kv.z), f2tf(kv.w) };
            *(uint4*)&Ks[r*LQ + c] = uk;
            float4 vv = *(const float4*)(Vg + (size_t)kv0*DK_ + idx);
            uint4 uv = { f2tf(vv.x), f2tf(vv.y), f2tf(vv.z), f2tf(vv.w) };
            *(uint4*)&Vs[r*LQ + c] = uv;
        }
        __syncthreads();

        // S = (Q*scale) @ K^T : warp tile 32x64
        float s[2][8][4] = {};
        #pragma unroll
        for (int kt = 0; kt < 8; kt++) {
            uint32_t bf[8][2];
            #pragma unroll
            for (int nt = 0; nt < 8; nt++) {
                bf[nt][0] = Ks[(nt*8 + g)*LQ + kt*8 + t    ];
                bf[nt][1] = Ks[(nt*8 + g)*LQ + kt*8 + t + 4];
            }
            #pragma unroll
            for (int mt = 0; mt < 2; mt++) {
                uint32_t af[4];
                int r = mw + mt*16 + g;
                af[0] = Qs[ r     *LQ + kt*8 + t    ];
                af[1] = Qs[(r + 8)*LQ + kt*8 + t    ];
                af[2] = Qs[ r     *LQ + kt*8 + t + 4];
                af[3] = Qs[(r + 8)*LQ + kt*8 + t + 4];
                #pragma unroll
                for (int nt = 0; nt < 8; nt++) mma8(s[mt][nt], af, bf[nt]);
            }
        }

        // Online softmax (row = shared by 4 lanes with same g; shfl width 4)
        #pragma unroll
        for (int mt = 0; mt < 2; mt++)
        #pragma unroll
        for (int hh = 0; hh < 2; hh++) {
            int ci = hh*2;
            float mx = -1e30f;
            #pragma unroll
            for (int nt = 0; nt < 8; nt++)
                mx = fmaxf(mx, fmaxf(s[mt][nt][ci], s[mt][nt][ci+1]));
            mx = fmaxf(mx, __shfl_xor_sync(0xffffffffu, mx, 1, 4));
            mx = fmaxf(mx, __shfl_xor_sync(0xffffffffu, mx, 2, 4));
            float mn = fmaxf(mi[mt][hh], mx);
            float al = __expf(mi[mt][hh] - mn);
            float rs = 0.f;
            int r = mw + mt*16 + hh*8 + g;
            #pragma unroll
            for (int nt = 0; nt < 8; nt++) {
                float p0 = __expf(s[mt][nt][ci]   - mn);
                float p1 = __expf(s[mt][nt][ci+1] - mn);
                rs += p0 + p1;
                uint2 pu = { f2tf(p0), f2tf(p1) };
                *(uint2*)&Ps[r*LQ + nt*8 + 2*t] = pu;
                o[mt][nt][ci]   *= al;
                o[mt][nt][ci+1] *= al;
            }
            rs += __shfl_xor_sync(0xffffffffu, rs, 1, 4);
            rs += __shfl_xor_sync(0xffffffffu, rs, 2, 4);
            li[mt][hh] = li[mt][hh]*al + rs;
            mi[mt][hh] = mn;
        }
        __syncwarp();   // P rows are warp-private; make STS visible to lanes

        // O += P @ V
        #pragma unroll
        for (int kt = 0; kt < 8; kt++) {
            uint32_t bv[8][2];
            #pragma unroll
            for (int nt = 0; nt < 8; nt++) {
                bv[nt][0] = Vs[(kt*8 + t    )*LQ + nt*8 + g];
                bv[nt][1] = Vs[(kt*8 + t + 4)*LQ + nt*8 + g];
            }
            #pragma unroll
            for (int mt = 0; mt < 2; mt++) {
                uint32_t pa[4];
                int r = mw + mt*16 + g;
                pa[0] = Ps[ r     *LQ + kt*8 + t    ];
                pa[1] = Ps[(r + 8)*LQ + kt*8 + t    ];
                pa[2] = Ps[ r     *LQ + kt*8 + t + 4];
                pa[3] = Ps[(r + 8)*LQ + kt*8 + t + 4];
                #pragma unroll
                for (int nt = 0; nt < 8; nt++) mma8(o[mt][nt], pa, bv[nt]);
            }
        }
    }

    // Normalize + write [B,T,D]
    #pragma unroll
    for (int mt = 0; mt < 2; mt++)
    #pragma unroll
    for (int hh = 0; hh < 2; hh++) {
        float inv = 1.f / li[mt][hh];
        int r = qtile*128 + mw + mt*16 + hh*8 + g;
        float* dst = g_O + ((size_t)b*T_ + r)*D_ + h*DK_;
        #pragma unroll
        for (int nt = 0; nt < 8; nt++) {
            float2 v = make_float2(o[mt][nt][hh*2]*inv, o[mt][nt][hh*2+1]*inv);
            *(float2*)(dst + nt*8 + 2*t) = v;
        }
    }
}

// ---------------------------------------------------------------------------
extern "C" void kernel_launch(void* const* d_in, const int* in_sizes, int n_in,
                              void* d_out, int out_size) {
    const float* x  = (const float*)d_in[0];
    const float* WQ = (const float*)d_in[1];
    const float* WK = (const float*)d_in[2];
    const float* WV = (const float*)d_in[3];
    const float* Wp = (const float*)d_in[4];
    float* out = (float*)d_out;

    cudaFuncSetAttribute(attn_mma,
                         cudaFuncAttributeMaxDynamicSharedMemorySize,
                         ATTN_SMEM_BYTES);

    dim3 gg(D_/64, M_/128);               // (12, 64)
    gemm_mma<<<gg, 128>>>(x, WQ, nullptr, 0);
    gemm_mma<<<gg, 128>>>(x, WK, nullptr, 1);
    gemm_mma<<<gg, 128>>>(x, WV, nullptr, 2);

    dim3 ga(T_/128, H_, B_);              // (32, 12, 2)
    attn_mma<<<ga, 128, ATTN_SMEM_BYTES>>>();

    gemm_mma<<<gg, 128>>>(nullptr, Wp, out, 3);
}

// round 6
// speedup vs baseline: 3.5437x; 1.1601x over previous
#include <cuda_runtime.h>
#include <cstdint>

#define B_  2
#define T_  4096
#define D_  768
#define H_  12
#define DK_ 64
#define M_  (B_*T_)   // 8192

// Scratch (allocation-free)
__device__ float g_Q[B_*H_*T_*DK_];
__device__ float g_K[B_*H_*T_*DK_];
__device__ float g_V[B_*H_*T_*DK_];
__device__ float g_O[M_*D_];

__device__ __forceinline__ uint32_t f2tf(float f) {
    uint32_t r; asm("cvt.rna.tf32.f32 %0, %1;" : "=r"(r) : "f"(f)); return r;
}
__device__ __forceinline__ float ex2f(float x) {
    float y; asm("ex2.approx.f32 %0, %1;" : "=f"(y) : "f"(x)); return y;
}
__device__ __forceinline__ void mma8(float* c, const uint32_t* a, const uint32_t* b) {
    asm volatile("mma.sync.aligned.m16n8k8.row.col.f32.tf32.tf32.f32 "
        "{%0,%1,%2,%3}, {%4,%5,%6,%7}, {%8,%9}, {%0,%1,%2,%3};"
        : "+f"(c[0]), "+f"(c[1]), "+f"(c[2]), "+f"(c[3])
        : "r"(a[0]), "r"(a[1]), "r"(a[2]), "r"(a[3]), "r"(b[0]), "r"(b[1]));
}

// ===========================================================================
// GEMM: C[8192,768] = A @ W. Block 128x128, k-step 32, 256 thr, 8 warps
// (warp tile 64x32). cp.async double-buffered raw fp32 smem; cvt at frag load.
// mode -1: z=blockIdx.z selects WQ/WK/WV -> g_Q/g_K/g_V split-head layout.
// mode  3: W0 -> row-major C. A==nullptr reads g_O.
// ===========================================================================
#define GSM_BYTES ((2*128*36 + 2*32*132) * 4)   // 36864 + 33792 = 70656

__global__ __launch_bounds__(256, 2) void gemm2(
        const float* __restrict__ A,
        const float* __restrict__ W0, const float* __restrict__ W1,
        const float* __restrict__ W2,
        float* __restrict__ C, int mode) {
    extern __shared__ float sg[];
    float* As = sg;                  // [2][128][36]
    float* Ws = sg + 2*128*36;       // [2][32][132]
    const float* Ar = A ? A : g_O;
    const int z = blockIdx.z;
    const float* W = (mode == 3) ? W0 : (z == 0 ? W0 : z == 1 ? W1 : W2);

    const int tid = threadIdx.x;
    const int w = tid >> 5, l = tid & 31, g = l >> 2, t = l & 3;
    const int wm = (w >> 2) * 64, wn = (w & 3) * 32;
    const int m0 = blockIdx.y * 128, n0 = blockIdx.x * 128;

    const uint32_t As_s = (uint32_t)__cvta_generic_to_shared(As);
    const uint32_t Ws_s = (uint32_t)__cvta_generic_to_shared(Ws);

    auto issue = [&](int ks, int buf) {
        #pragma unroll
        for (int j = 0; j < 4; j++) {             // A tile 128x32 (m-major)
            int id = j*256 + tid;
            int m = id >> 3, kq = id & 7;
            uint32_t dst = As_s + (uint32_t)(((buf*128 + m)*36 + kq*4) * 4);
            const float* src = Ar + (size_t)(m0 + m)*D_ + ks*32 + kq*4;
            asm volatile("cp.async.cg.shared.global [%0], [%1], 16;\n"
                         :: "r"(dst), "l"(src));
        }
        #pragma unroll
        for (int j = 0; j < 4; j++) {             // W tile 32x128 (k-major)
            int id = j*256 + tid;
            int k = id >> 5, nq = id & 31;
            uint32_t dst = Ws_s + (uint32_t)(((buf*32 + k)*132 + nq*4) * 4);
            const float* src = W + (size_t)(ks*32 + k)*D_ + n0 + nq*4;
            asm volatile("cp.async.cg.shared.global [%0], [%1], 16;\n"
                         :: "r"(dst), "l"(src));
        }
        asm volatile("cp.async.commit_group;\n");
    };

    float acc[4][4][4] = {};
    issue(0, 0);
    for (int s = 0; s < 24; s++) {
        const int buf = s & 1;
        if (s + 1 < 24) {
            issue(s + 1, (s + 1) & 1);
            asm volatile("cp.async.wait_group 1;\n");
        } else {
            asm volatile("cp.async.wait_group 0;\n");
        }
        __syncthreads();
        const float* Ab = As + buf*128*36;
        const float* Wb = Ws + buf*32*132;
        #pragma unroll
        for (int kt = 0; kt < 4; kt++) {
            uint32_t bf[4][2];
            #pragma unroll
            for (int nt = 0; nt < 4; nt++) {
                bf[nt][0] = f2tf(Wb[(kt*8 + t    )*132 + wn + nt*8 + g]);
                bf[nt][1] = f2tf(Wb[(kt*8 + t + 4)*132 + wn + nt*8 + g]);
            }
            #pragma unroll
            for (int mt = 0; mt < 4; mt++) {
                uint32_t af[4];
                int r = wm + mt*16 + g;
                af[0] = f2tf(Ab[ r     *36 + kt*8 + t    ]);
                af[1] = f2tf(Ab[(r + 8)*36 + kt*8 + t    ]);
                af[2] = f2tf(Ab[ r     *36 + kt*8 + t + 4]);
                af[3] = f2tf(Ab[(r + 8)*36 + kt*8 + t + 4]);
                #pragma unroll
                for (int nt = 0; nt < 4; nt++) mma8(acc[mt][nt], af, bf[nt]);
            }
        }
        __syncthreads();
    }

    #pragma unroll
    for (int mt = 0; mt < 4; mt++)
    #pragma unroll
    for (int hh = 0; hh < 2; hh++) {
        int m = m0 + wm + mt*16 + hh*8 + g;
        #pragma unroll
        for (int nt = 0; nt < 4; nt++) {
            int n = n0 + wn + nt*8 + 2*t;
            float2 v = make_float2(acc[mt][nt][hh*2], acc[mt][nt][hh*2 + 1]);
            if (mode == 3) {
                *(float2*)(C + (size_t)m*D_ + n) = v;
            } else {
                float* out = (z == 0) ? g_Q : (z == 1) ? g_K : g_V;
                int h = n >> 6, dk = n & 63;
                int b = m >> 12, tt = m & 4095;
                *(float2*)(out + ((size_t)(b*H_ + h)*T_ + tt)*DK_ + dk) = v;
            }
        }
    }
}

// ===========================================================================
// Flash attention, tf32 mma, interleaved softmax+PV.
// Block = (b,h,128 Q rows), 4 warps (warp 32 rows), Bc=64.
// Q staged with 0.125*log2(e) folded in -> raw ex2 softmax.
// P: per-warp double-buffered 32x10 mini-tile (raw fp32 bits = tf32 RZ).
// ===========================================================================
#define LQ 68
#define PMW 320   // 32 rows * 10 floats, per warp per parity
#define ASM_BYTES (((128 + 64 + 64)*LQ)*4 + 4*2*PMW*4)   // 69632+10240=79872

__global__ __launch_bounds__(128) void attn2() {
    extern __shared__ float sa[];
    uint32_t* Qs = (uint32_t*)sa;          // [128][68] tf32(Q*0.1803)
    uint32_t* Ks = Qs + 128*LQ;            // [64][68]  tf32
    uint32_t* Vs = Ks + 64*LQ;             // [64][68]  tf32
    float*    Pm = (float*)(Vs + 64*LQ);   // [4 warps][2 buf][32][10]

    const int qtile = blockIdx.x, h = blockIdx.y, b = blockIdx.z;
    const int tid = threadIdx.x;
    const int w = tid >> 5, l = tid & 31, g = l >> 2, t = l & 3;
    const int mw = w * 32;

    const float* Qg = g_Q + ((size_t)(b*H_ + h)*T_ + (size_t)qtile*128) * DK_;
    const float* Kg = g_K + (size_t)(b*H_ + h)*T_ * DK_;
    const float* Vg = g_V + (size_t)(b*H_ + h)*T_ * DK_;

    const float QSC = 0.180336881f;        // 0.125 * log2(e)
    #pragma unroll
    for (int it = 0; it < 16; it++) {
        int idx = it*512 + tid*4;
        int r = idx >> 6, c = idx & 63;
        float4 v = *(const float4*)(Qg + idx);
        uint4 u = { f2tf(v.x*QSC), f2tf(v.y*QSC), f2tf(v.z*QSC), f2tf(v.w*QSC) };
        *(uint4*)&Qs[r*LQ + c] = u;
    }

    float o[2][8][4] = {};
    float mi[2][2] = {{-1e30f,-1e30f},{-1e30f,-1e30f}};
    float li[2][2] = {};

    for (int kv0 = 0; kv0 < T_; kv0 += 64) {
        __syncthreads();
        #pragma unroll
        for (int it = 0; it < 8; it++) {
            int idx = it*512 + tid*4;
            int r = idx >> 6, c = idx & 63;
            float4 kv = *(const float4*)(Kg + (size_t)kv0*DK_ + idx);
            uint4 uk = { f2tf(kv.x), f2tf(kv.y), f2tf(kv.z), f2tf(kv.w) };
            *(uint4*)&Ks[r*LQ + c] = uk;
            float4 vv = *(const float4*)(Vg + (size_t)kv0*DK_ + idx);
            uint4 uv = { f2tf(vv.x), f2tf(vv.y), f2tf(vv.z), f2tf(vv.w) };
            *(uint4*)&Vs[r*LQ + c] = uv;
        }
        __syncthreads();

        // ---- S = Q @ K^T (scores already in log2 domain via Q scale) ----
        float s[2][8][4] = {};
        #pragma unroll
        for (int kt = 0; kt < 8; kt++) {
            uint32_t bf[8][2];
            #pragma unroll
            for (int nt = 0; nt < 8; nt++) {
                bf[nt][0] = Ks[(nt*8 + g)*LQ + kt*8 + t    ];
                bf[nt][1] = Ks[(nt*8 + g)*LQ + kt*8 + t + 4];
            }
            #pragma unroll
            for (int mt = 0; mt < 2; mt++) {
                uint32_t af[4];
                int r = mw + mt*16 + g;
                af[0] = Qs[ r     *LQ + kt*8 + t    ];
                af[1] = Qs[(r + 8)*LQ + kt*8 + t    ];
                af[2] = Qs[ r     *LQ + kt*8 + t + 4];
                af[3] = Qs[(r + 8)*LQ + kt*8 + t + 4];
                #pragma unroll
                for (int nt = 0; nt < 8; nt++) mma8(s[mt][nt], af, bf[nt]);
            }
        }

        // ---- phase 1: row max, alpha, rescale O ----
        float al[2][2], mnr[2][2];
        #pragma unroll
        for (int mt = 0; mt < 2; mt++)
        #pragma unroll
        for (int hh = 0; hh < 2; hh++) {
            int ci = hh*2;
            float mx = -1e30f;
            #pragma unroll
            for (int nt = 0; nt < 8; nt++)
                mx = fmaxf(mx, fmaxf(s[mt][nt][ci], s[mt][nt][ci+1]));
            mx = fmaxf(mx, __shfl_xor_sync(0xffffffffu, mx, 1, 4));
            mx = fmaxf(mx, __shfl_xor_sync(0xffffffffu, mx, 2, 4));
            float mn = fmaxf(mi[mt][hh], mx);
            float a  = ex2f(mi[mt][hh] - mn);
            al[mt][hh] = a; mnr[mt][hh] = mn; mi[mt][hh] = mn;
            #pragma unroll
            for (int nt = 0; nt < 8; nt++) {
                o[mt][nt][ci]   *= a;
                o[mt][nt][ci+1] *= a;
            }
        }

        // ---- phase 2: per 8-col tile: exp -> mini-P -> PV mma ----
        float rs[2][2] = {};
        #pragma unroll
        for (int kt = 0; kt < 8; kt++) {
            float* Pw = Pm + (w*2 + (kt & 1))*PMW;
            #pragma unroll
            for (int mt = 0; mt < 2; mt++) {
                float p0 = ex2f(s[mt][kt][0] - mnr[mt][0]);
                float p1 = ex2f(s[mt][kt][1] - mnr[mt][0]);
                float p2 = ex2f(s[mt][kt][2] - mnr[mt][1]);
                float p3 = ex2f(s[mt][kt][3] - mnr[mt][1]);
                rs[mt][0] += p0 + p1;
                rs[mt][1] += p2 + p3;
                int rb = mt*16 + g;
                *(float2*)&Pw[ rb     *10 + 2*t] = make_float2(p0, p1);
                *(float2*)&Pw[(rb + 8)*10 + 2*t] = make_float2(p2, p3);
            }
            __syncwarp();
            uint32_t bv[8][2];
            #pragma unroll
            for (int nt = 0; nt < 8; nt++) {
                bv[nt][0] = Vs[(kt*8 + t    )*LQ + nt*8 + g];
                bv[nt][1] = Vs[(kt*8 + t + 4)*LQ + nt*8 + g];
            }
            #pragma unroll
            for (int mt = 0; mt < 2; mt++) {
                uint32_t pa[4];
                int rb = mt*16 + g;
                pa[0] = __float_as_uint(Pw[ rb     *10 + t    ]);
                pa[1] = __float_as_uint(Pw[(rb + 8)*10 + t    ]);
                pa[2] = __float_as_uint(Pw[ rb     *10 + t + 4]);
                pa[3] = __float_as_uint(Pw[(rb + 8)*10 + t + 4]);
                #pragma unroll
                for (int nt = 0; nt < 8; nt++) mma8(o[mt][nt], pa, bv[nt]);
            }
        }

        #pragma unroll
        for (int mt = 0; mt < 2; mt++)
        #pragma unroll
        for (int hh = 0; hh < 2; hh++) {
            float r = rs[mt][hh];
            r += __shfl_xor_sync(0xffffffffu, r, 1, 4);
            r += __shfl_xor_sync(0xffffffffu, r, 2, 4);
            li[mt][hh] = li[mt][hh]*al[mt][hh] + r;
        }
    }

    #pragma unroll
    for (int mt = 0; mt < 2; mt++)
    #pragma unroll
    for (int hh = 0; hh < 2; hh++) {
        float inv = 1.f / li[mt][hh];
        int r = qtile*128 + mw + mt*16 + hh*8 + g;
        float* dst = g_O + ((size_t)b*T_ + r)*D_ + h*DK_;
        #pragma unroll
        for (int nt = 0; nt < 8; nt++) {
            float2 v = make_float2(o[mt][nt][hh*2]*inv, o[mt][nt][hh*2+1]*inv);
            *(float2*)(dst + nt*8 + 2*t) = v;
        }
    }
}

// ===========================================================================
extern "C" void kernel_launch(void* const* d_in, const int* in_sizes, int n_in,
                              void* d_out, int out_size) {
    const float* x  = (const float*)d_in[0];
    const float* WQ = (const float*)d_in[1];
    const float* WK = (const float*)d_in[2];
    const float* WV = (const float*)d_in[3];
    const float* Wp = (const float*)d_in[4];
    float* out = (float*)d_out;

    cudaFuncSetAttribute(gemm2, cudaFuncAttributeMaxDynamicSharedMemorySize,
                         GSM_BYTES);
    cudaFuncSetAttribute(attn2, cudaFuncAttributeMaxDynamicSharedMemorySize,
                         ASM_BYTES);

    dim3 gq(D_/128, M_/128, 3);           // (6, 64, 3) fused QKV
    gemm2<<<gq, 256, GSM_BYTES>>>(x, WQ, WK, WV, nullptr, -1);

    dim3 ga(T_/128, H_, B_);              // (32, 12, 2)
    attn2<<<ga, 128, ASM_BYTES>>>();

    dim3 gp(D_/128, M_/128, 1);
    gemm2<<<gp, 256, GSM_BYTES>>>(nullptr, Wp, Wp, Wp, out, 3);
}